// round 12
// baseline (speedup 1.0000x reference)
#include <cuda_runtime.h>
#include <cuda_bf16.h>
#include <cstdint>

#define MB_    8192
#define DIN_   4096
#define RANK_  2048
#define UNITS_ 4096

#define BM 128
#define BN 256
#define BK 32
#define NSTAGE 3
#define NTHR 256

// SMEM rows padded to 80B (5 x 16B) -> ldmatrix conflict-free
#define ROWB 80
#define ATILEB (128 * ROWB)              /* 10240 B */
#define BTILEB (256 * ROWB)              /* 20480 B */
#define STAGEB (2 * ATILEB + 2 * BTILEB) /* 61440 B */
#define SMEMB (NSTAGE * STAGEB)          /* 184320 B */
#define OFF_AH 0
#define OFF_AL ATILEB
#define OFF_BH (2 * ATILEB)
#define OFF_BL (2 * ATILEB + BTILEB)

// ---------------- device scratch (no cudaMalloc allowed) ----------------
__device__ __nv_bfloat16 g_Xh[(size_t)MB_ * DIN_];
__device__ __nv_bfloat16 g_Xl[(size_t)MB_ * DIN_];
__device__ __nv_bfloat16 g_Uth[(size_t)RANK_ * DIN_];   // (U*diag(S))^T, [RANK, DIN]
__device__ __nv_bfloat16 g_Utl[(size_t)RANK_ * DIN_];
__device__ __nv_bfloat16 g_Vh[(size_t)UNITS_ * RANK_];  // V already [N, K]
__device__ __nv_bfloat16 g_Vl[(size_t)UNITS_ * RANK_];
__device__ __nv_bfloat16 g_Hh[(size_t)MB_ * RANK_];
__device__ __nv_bfloat16 g_Hl[(size_t)MB_ * RANK_];

// ---------------- helpers ----------------
__device__ __forceinline__ uint32_t su32(const void* p) {
    uint32_t a;
    asm("{ .reg .u64 t; cvta.to.shared.u64 t, %1; cvt.u32.u64 %0, t; }" : "=r"(a) : "l"(p));
    return a;
}
__device__ __forceinline__ void cp16(uint32_t d, const void* g) {
    asm volatile("cp.async.cg.shared.global [%0], [%1], 16;" :: "r"(d), "l"(g));
}
__device__ __forceinline__ void ldsm4(uint32_t& r0, uint32_t& r1, uint32_t& r2, uint32_t& r3,
                                      uint32_t addr) {
    asm volatile("ldmatrix.sync.aligned.m8n8.x4.shared.b16 {%0,%1,%2,%3}, [%4];"
                 : "=r"(r0), "=r"(r1), "=r"(r2), "=r"(r3) : "r"(addr));
}
__device__ __forceinline__ void mma16816(float* c, uint32_t a0, uint32_t a1, uint32_t a2,
                                         uint32_t a3, uint32_t b0, uint32_t b1) {
    asm volatile(
        "mma.sync.aligned.m16n8k16.row.col.f32.bf16.bf16.f32 "
        "{%0,%1,%2,%3}, {%4,%5,%6,%7}, {%8,%9}, {%0,%1,%2,%3};"
        : "+f"(c[0]), "+f"(c[1]), "+f"(c[2]), "+f"(c[3])
        : "r"(a0), "r"(a1), "r"(a2), "r"(a3), "r"(b0), "r"(b1));
}
__device__ __forceinline__ uint32_t pack_hi(float x, float y) {
    __nv_bfloat162 t(__float2bfloat16(x), __float2bfloat16(y));
    return *reinterpret_cast<uint32_t*>(&t);
}
__device__ __forceinline__ uint32_t pack_lo(float x, float y) {
    __nv_bfloat16 hx = __float2bfloat16(x), hy = __float2bfloat16(y);
    __nv_bfloat162 t(__float2bfloat16(x - __bfloat162float(hx)),
                     __float2bfloat16(y - __bfloat162float(hy)));
    return *reinterpret_cast<uint32_t*>(&t);
}

// ---------------- conversion kernels ----------------
__global__ void split_kernel(const float* __restrict__ src,
                             __nv_bfloat16* __restrict__ hi,
                             __nv_bfloat16* __restrict__ lo, int n4) {
    int i = blockIdx.x * blockDim.x + threadIdx.x;
    if (i >= n4) return;
    float4 v = reinterpret_cast<const float4*>(src)[i];
    uint2 hu = { pack_hi(v.x, v.y), pack_hi(v.z, v.w) };
    uint2 lu = { pack_lo(v.x, v.y), pack_lo(v.z, v.w) };
    reinterpret_cast<uint2*>(hi)[i] = hu;
    reinterpret_cast<uint2*>(lo)[i] = lu;
}

// Ut = (U * diag(S))^T split to bf16 hi/lo.  U: [DIN, RANK] row-major.
__global__ void uprep_kernel(const float* __restrict__ U, const float* __restrict__ S) {
    __shared__ float t[32][33];
    int n0 = blockIdx.x * 32, k0 = blockIdx.y * 32;
    int tx = threadIdx.x, ty = threadIdx.y;
    float sv = S[n0 + tx];
#pragma unroll
    for (int i = 0; i < 4; i++)
        t[ty + i * 8][tx] = U[(size_t)(k0 + ty + i * 8) * RANK_ + n0 + tx] * sv;
    __syncthreads();
#pragma unroll
    for (int i = 0; i < 4; i++) {
        int n = n0 + ty + i * 8, k = k0 + tx;
        float v = t[tx][ty + i * 8];
        __nv_bfloat16 h = __float2bfloat16(v);
        __nv_bfloat16 l = __float2bfloat16(v - __bfloat162float(h));
        g_Uth[(size_t)n * DIN_ + k] = h;
        g_Utl[(size_t)n * DIN_ + k] = l;
    }
}

// ---------------- GEMM ----------------
// A tiles: 128 rows x 4 segs = 512 cp16 each (2 iters of 256)
// B tiles: 256 rows x 4 segs = 1024 cp16 each (4 iters of 256)
__device__ __forceinline__ void load_stage(uint32_t st,
                                           const __nv_bfloat16* a0, const __nv_bfloat16* a1,
                                           const __nv_bfloat16* b0, const __nv_bfloat16* b1,
                                           int K, int tid) {
#pragma unroll
    for (int i = 0; i < 2; i++) {
        const int op = tid + i * 256;
        const int r = op >> 2, seg = op & 3;
        const uint32_t so = (uint32_t)r * ROWB + seg * 16;
        const size_t go = (size_t)r * K + seg * 8;
        cp16(st + OFF_AH + so, a0 + go);
        cp16(st + OFF_AL + so, a1 + go);
    }
#pragma unroll
    for (int i = 0; i < 4; i++) {
        const int op = tid + i * 256;
        const int r = op >> 2, seg = op & 3;
        const uint32_t so = (uint32_t)r * ROWB + seg * 16;
        const size_t go = (size_t)r * K + seg * 8;
        cp16(st + OFF_BH + so, b0 + go);
        cp16(st + OFF_BL + so, b1 + go);
    }
    asm volatile("cp.async.commit_group;" ::: "memory");
}

template <int MODE>
__global__ void __launch_bounds__(NTHR, 1)
gemm_kernel(const float* __restrict__ bias, float* __restrict__ out) {
    constexpr int K = (MODE == 0) ? DIN_ : RANK_;
    constexpr int NC = K / BK;

    extern __shared__ __align__(128) char smem[];
    const uint32_t sb = su32(smem);
    const int tid = threadIdx.x;
    const int lane = tid & 31;
    const int warp = tid >> 5;       // 0..7
    const int wm = warp >> 2;        // 0..1  (64-row slabs)
    const int wn = warp & 3;         // 0..3  (64-col slabs)
    const size_t m0 = (size_t)blockIdx.y * BM;
    const size_t n0 = (size_t)blockIdx.x * BN;

    const __nv_bfloat16 *Ah, *Al, *Bh, *Bl;
    if (MODE == 0) { Ah = g_Xh; Al = g_Xl; Bh = g_Uth; Bl = g_Utl; }
    else           { Ah = g_Hh; Al = g_Hl; Bh = g_Vh;  Bl = g_Vl;  }
    const __nv_bfloat16* a0 = Ah + m0 * K;
    const __nv_bfloat16* a1 = Al + m0 * K;
    const __nv_bfloat16* b0 = Bh + n0 * K;
    const __nv_bfloat16* b1 = Bl + n0 * K;

    // prologue: stages 0 and 1
    load_stage(sb + 0 * STAGEB, a0, a1, b0, b1, K, tid);
    load_stage(sb + 1 * STAGEB, a0 + BK, a1 + BK, b0 + BK, b1 + BK, K, tid);

    // warp tile 64x64: acc[mt 0..3][nt 0..7][4] = 128 regs
    float acc[4][8][4];
#pragma unroll
    for (int i = 0; i < 4; i++)
#pragma unroll
        for (int j = 0; j < 8; j++)
#pragma unroll
            for (int q = 0; q < 4; q++) acc[i][j][q] = 0.0f;

    const int lrow = lane & 15;
    const int lhalf = (lane >> 4) * 16;
    const uint32_t aLane = (uint32_t)(wm * 64 + lrow) * ROWB + lhalf;
    const uint32_t bLane = (uint32_t)(wn * 64 + lrow) * ROWB + lhalf;

    uint32_t curStage = sb;
    uint32_t pfStage  = sb + 2 * STAGEB;
    const uint32_t ringEnd = sb + NSTAGE * STAGEB;

    for (int c = 0; c < NC; c++) {
        if (c + 1 < NC) asm volatile("cp.async.wait_group 1;" ::: "memory");
        else            asm volatile("cp.async.wait_group 0;" ::: "memory");
        __syncthreads();

        if (c + 2 < NC) {
            const int kn = (c + 2) * BK;
            load_stage(pfStage, a0 + kn, a1 + kn, b0 + kn, b1 + kn, K, tid);
        }
        pfStage += STAGEB; if (pfStage == ringEnd) pfStage = sb;

        const uint32_t aBase = curStage + aLane;
        const uint32_t bBase = curStage + bLane;
        curStage += STAGEB; if (curStage == ringEnd) curStage = sb;

#pragma unroll
        for (int ks = 0; ks < 2; ks++) {
            const uint32_t ko = ks * 32;   // 16 bf16 per k-step
            // B frags for 64 cols: 4 ldsm4 (hi) + 4 ldsm4 (lo) = 32 regs
            uint32_t bh[16], bl[16];
#pragma unroll
            for (int g = 0; g < 4; g++) {
                ldsm4(bh[g * 4 + 0], bh[g * 4 + 1], bh[g * 4 + 2], bh[g * 4 + 3],
                      bBase + OFF_BH + (uint32_t)g * 16 * ROWB + ko);
                ldsm4(bl[g * 4 + 0], bl[g * 4 + 1], bl[g * 4 + 2], bl[g * 4 + 3],
                      bBase + OFF_BL + (uint32_t)g * 16 * ROWB + ko);
            }
#pragma unroll
            for (int mt = 0; mt < 4; mt++) {
                uint32_t ah[4], al[4];
                ldsm4(ah[0], ah[1], ah[2], ah[3],
                      aBase + OFF_AH + (uint32_t)mt * 16 * ROWB + ko);
                ldsm4(al[0], al[1], al[2], al[3],
                      aBase + OFF_AL + (uint32_t)mt * 16 * ROWB + ko);
#pragma unroll
                for (int nt = 0; nt < 8; nt++) {
                    const int g = nt >> 1, o = nt & 1;
                    const uint32_t bb0 = bh[g * 4 + o];
                    const uint32_t bb1 = bh[g * 4 + o + 2];
                    const uint32_t cb0 = bl[g * 4 + o];
                    const uint32_t cb1 = bl[g * 4 + o + 2];
                    float* cc = acc[mt][nt];
                    mma16816(cc, ah[0], ah[1], ah[2], ah[3], bb0, bb1);  // Ah*Bh
                    mma16816(cc, al[0], al[1], al[2], al[3], bb0, bb1);  // Al*Bh
                    mma16816(cc, ah[0], ah[1], ah[2], ah[3], cb0, cb1);  // Ah*Bl
                }
            }
        }
    }

    // ---------------- epilogue ----------------
    const int crow = lane >> 2;          // 0..7
    const int ccol = (lane & 3) * 2;     // 0,2,4,6
#pragma unroll
    for (int mt = 0; mt < 4; mt++) {
#pragma unroll
        for (int nt = 0; nt < 8; nt++) {
            const float* cc = acc[mt][nt];
            const size_t m = m0 + wm * 64 + mt * 16 + crow;
            const size_t n = n0 + wn * 64 + nt * 8 + ccol;
            if (MODE == 0) {
                *reinterpret_cast<uint32_t*>(g_Hh + m * RANK_ + n) = pack_hi(cc[0], cc[1]);
                *reinterpret_cast<uint32_t*>(g_Hl + m * RANK_ + n) = pack_lo(cc[0], cc[1]);
                *reinterpret_cast<uint32_t*>(g_Hh + (m + 8) * RANK_ + n) = pack_hi(cc[2], cc[3]);
                *reinterpret_cast<uint32_t*>(g_Hl + (m + 8) * RANK_ + n) = pack_lo(cc[2], cc[3]);
            } else {
                const float bv0 = __ldg(bias + n), bv1 = __ldg(bias + n + 1);
                float2 o0 = { fmaxf(cc[0] + bv0, 0.0f), fmaxf(cc[1] + bv1, 0.0f) };
                float2 o1 = { fmaxf(cc[2] + bv0, 0.0f), fmaxf(cc[3] + bv1, 0.0f) };
                *reinterpret_cast<float2*>(out + m * UNITS_ + n) = o0;
                *reinterpret_cast<float2*>(out + (m + 8) * UNITS_ + n) = o1;
            }
        }
    }
}

// ---------------- launch ----------------
extern "C" void kernel_launch(void* const* d_in, const int* in_sizes, int n_in,
                              void* d_out, int out_size) {
    const float* X    = (const float*)d_in[0];
    const float* U    = (const float*)d_in[1];
    const float* S    = (const float*)d_in[2];
    const float* V    = (const float*)d_in[3];
    const float* bias = (const float*)d_in[4];
    float* out = (float*)d_out;

    void *pXh, *pXl, *pVh, *pVl;
    cudaGetSymbolAddress(&pXh, g_Xh);
    cudaGetSymbolAddress(&pXl, g_Xl);
    cudaGetSymbolAddress(&pVh, g_Vh);
    cudaGetSymbolAddress(&pVl, g_Vl);

    split_kernel<<<(MB_ * DIN_ / 4 + 255) / 256, 256>>>(
        X, (__nv_bfloat16*)pXh, (__nv_bfloat16*)pXl, MB_ * DIN_ / 4);
    split_kernel<<<(UNITS_ * RANK_ / 4 + 255) / 256, 256>>>(
        V, (__nv_bfloat16*)pVh, (__nv_bfloat16*)pVl, UNITS_ * RANK_ / 4);
    uprep_kernel<<<dim3(RANK_ / 32, DIN_ / 32), dim3(32, 8)>>>(U, S);

    cudaFuncSetAttribute(gemm_kernel<0>, cudaFuncAttributeMaxDynamicSharedMemorySize, SMEMB);
    cudaFuncSetAttribute(gemm_kernel<1>, cudaFuncAttributeMaxDynamicSharedMemorySize, SMEMB);

    // GEMM1: H = (X @ U) * S  (S folded into U^T), split-stored to g_Hh/g_Hl
    gemm_kernel<0><<<dim3(RANK_ / BN, MB_ / BM), NTHR, SMEMB>>>(nullptr, nullptr);
    // GEMM2: out = relu(H @ V^T + bias)
    gemm_kernel<1><<<dim3(UNITS_ / BN, MB_ / BM), NTHR, SMEMB>>>(bias, out);
}

// round 14
// speedup vs baseline: 1.1000x; 1.1000x over previous
#include <cuda_runtime.h>
#include <cuda_bf16.h>
#include <cstdint>

#define MB_    8192
#define DIN_   4096
#define RANK_  2048
#define UNITS_ 4096

#define BM 256
#define BN 128
#define BK 64
#define NSTAGE 2
#define NTHR 512

// SMEM rows: 128B data padded to 144B (9 x 16B, gcd(9,8)=1) -> ldmatrix conflict-free
#define ROWB 144
#define ATILEB (256 * ROWB)              /* 36864 B */
#define BTILEB (128 * ROWB)              /* 18432 B */
#define STAGEB (2 * ATILEB + 2 * BTILEB) /* 110592 B */
#define SMEMB (NSTAGE * STAGEB)          /* 221184 B */
#define OFF_AH 0
#define OFF_AL ATILEB
#define OFF_BH (2 * ATILEB)
#define OFF_BL (2 * ATILEB + BTILEB)

// ---------------- device scratch (no cudaMalloc allowed) ----------------
__device__ __nv_bfloat16 g_Xh[(size_t)MB_ * DIN_];
__device__ __nv_bfloat16 g_Xl[(size_t)MB_ * DIN_];
__device__ __nv_bfloat16 g_Uth[(size_t)RANK_ * DIN_];   // (U*diag(S))^T, [RANK, DIN]
__device__ __nv_bfloat16 g_Utl[(size_t)RANK_ * DIN_];
__device__ __nv_bfloat16 g_Vh[(size_t)UNITS_ * RANK_];  // V already [N, K]
__device__ __nv_bfloat16 g_Vl[(size_t)UNITS_ * RANK_];
__device__ __nv_bfloat16 g_Hh[(size_t)MB_ * RANK_];
__device__ __nv_bfloat16 g_Hl[(size_t)MB_ * RANK_];

// ---------------- helpers ----------------
__device__ __forceinline__ uint32_t su32(const void* p) {
    uint32_t a;
    asm("{ .reg .u64 t; cvta.to.shared.u64 t, %1; cvt.u32.u64 %0, t; }" : "=r"(a) : "l"(p));
    return a;
}
__device__ __forceinline__ void cp16(uint32_t d, const void* g) {
    asm volatile("cp.async.cg.shared.global [%0], [%1], 16;" :: "r"(d), "l"(g));
}
__device__ __forceinline__ void ldsm4(uint32_t& r0, uint32_t& r1, uint32_t& r2, uint32_t& r3,
                                      uint32_t addr) {
    asm volatile("ldmatrix.sync.aligned.m8n8.x4.shared.b16 {%0,%1,%2,%3}, [%4];"
                 : "=r"(r0), "=r"(r1), "=r"(r2), "=r"(r3) : "r"(addr));
}
__device__ __forceinline__ void mma16816(float* c, uint32_t a0, uint32_t a1, uint32_t a2,
                                         uint32_t a3, uint32_t b0, uint32_t b1) {
    asm volatile(
        "mma.sync.aligned.m16n8k16.row.col.f32.bf16.bf16.f32 "
        "{%0,%1,%2,%3}, {%4,%5,%6,%7}, {%8,%9}, {%0,%1,%2,%3};"
        : "+f"(c[0]), "+f"(c[1]), "+f"(c[2]), "+f"(c[3])
        : "r"(a0), "r"(a1), "r"(a2), "r"(a3), "r"(b0), "r"(b1));
}
__device__ __forceinline__ uint32_t pack_hi(float x, float y) {
    __nv_bfloat162 t(__float2bfloat16(x), __float2bfloat16(y));
    return *reinterpret_cast<uint32_t*>(&t);
}
__device__ __forceinline__ uint32_t pack_lo(float x, float y) {
    __nv_bfloat16 hx = __float2bfloat16(x), hy = __float2bfloat16(y);
    __nv_bfloat162 t(__float2bfloat16(x - __bfloat162float(hx)),
                     __float2bfloat16(y - __bfloat162float(hy)));
    return *reinterpret_cast<uint32_t*>(&t);
}

// ---------------- conversion kernels ----------------
__global__ void split_kernel(const float* __restrict__ src,
                             __nv_bfloat16* __restrict__ hi,
                             __nv_bfloat16* __restrict__ lo, int n4) {
    int i = blockIdx.x * blockDim.x + threadIdx.x;
    if (i >= n4) return;
    float4 v = reinterpret_cast<const float4*>(src)[i];
    uint2 hu = { pack_hi(v.x, v.y), pack_hi(v.z, v.w) };
    uint2 lu = { pack_lo(v.x, v.y), pack_lo(v.z, v.w) };
    reinterpret_cast<uint2*>(hi)[i] = hu;
    reinterpret_cast<uint2*>(lo)[i] = lu;
}

// Ut = (U * diag(S))^T split to bf16 hi/lo.  U: [DIN, RANK] row-major.
__global__ void uprep_kernel(const float* __restrict__ U, const float* __restrict__ S) {
    __shared__ float t[32][33];
    int n0 = blockIdx.x * 32, k0 = blockIdx.y * 32;
    int tx = threadIdx.x, ty = threadIdx.y;
    float sv = S[n0 + tx];
#pragma unroll
    for (int i = 0; i < 4; i++)
        t[ty + i * 8][tx] = U[(size_t)(k0 + ty + i * 8) * RANK_ + n0 + tx] * sv;
    __syncthreads();
#pragma unroll
    for (int i = 0; i < 4; i++) {
        int n = n0 + ty + i * 8, k = k0 + tx;
        float v = t[tx][ty + i * 8];
        __nv_bfloat16 h = __float2bfloat16(v);
        __nv_bfloat16 l = __float2bfloat16(v - __bfloat162float(h));
        g_Uth[(size_t)n * DIN_ + k] = h;
        g_Utl[(size_t)n * DIN_ + k] = l;
    }
}

// ---------------- GEMM ----------------
// A tiles: 256 rows x 8 segs = 2048 cp16 each (4 iters of 512)
// B tiles: 128 rows x 8 segs = 1024 cp16 each (2 iters of 512)
__device__ __forceinline__ void load_stage(uint32_t st,
                                           const __nv_bfloat16* a0, const __nv_bfloat16* a1,
                                           const __nv_bfloat16* b0, const __nv_bfloat16* b1,
                                           int K, int tid) {
#pragma unroll
    for (int i = 0; i < 4; i++) {
        const int op = tid + i * 512;
        const int r = op >> 3, seg = op & 7;
        const uint32_t so = (uint32_t)r * ROWB + seg * 16;
        const size_t go = (size_t)r * K + seg * 8;
        cp16(st + OFF_AH + so, a0 + go);
        cp16(st + OFF_AL + so, a1 + go);
    }
#pragma unroll
    for (int i = 0; i < 2; i++) {
        const int op = tid + i * 512;
        const int r = op >> 3, seg = op & 7;
        const uint32_t so = (uint32_t)r * ROWB + seg * 16;
        const size_t go = (size_t)r * K + seg * 8;
        cp16(st + OFF_BH + so, b0 + go);
        cp16(st + OFF_BL + so, b1 + go);
    }
    asm volatile("cp.async.commit_group;" ::: "memory");
}

template <int MODE>
__global__ void __launch_bounds__(NTHR, 1)
gemm_kernel(const float* __restrict__ bias, float* __restrict__ out) {
    constexpr int K = (MODE == 0) ? DIN_ : RANK_;
    constexpr int NC = K / BK;

    extern __shared__ __align__(128) char smem[];
    const uint32_t sb = su32(smem);
    const int tid = threadIdx.x;
    const int lane = tid & 31;
    const int warp = tid >> 5;       // 0..15
    const int wm = warp >> 2;        // 0..3  (64-row slabs)
    const int wn = warp & 3;         // 0..3  (32-col slabs)
    const size_t m0 = (size_t)blockIdx.y * BM;
    const size_t n0 = (size_t)blockIdx.x * BN;

    const __nv_bfloat16 *Ah, *Al, *Bh, *Bl;
    if (MODE == 0) { Ah = g_Xh; Al = g_Xl; Bh = g_Uth; Bl = g_Utl; }
    else           { Ah = g_Hh; Al = g_Hl; Bh = g_Vh;  Bl = g_Vl;  }
    const __nv_bfloat16* a0 = Ah + m0 * K;
    const __nv_bfloat16* a1 = Al + m0 * K;
    const __nv_bfloat16* b0 = Bh + n0 * K;
    const __nv_bfloat16* b1 = Bl + n0 * K;

    load_stage(sb, a0, a1, b0, b1, K, tid);

    // warp tile 64x32: acc[mt 0..3][nt 0..3][4] = 64 regs
    float acc[4][4][4];
#pragma unroll
    for (int i = 0; i < 4; i++)
#pragma unroll
        for (int j = 0; j < 4; j++)
#pragma unroll
            for (int q = 0; q < 4; q++) acc[i][j][q] = 0.0f;

    const int lrow = lane & 15;
    const int lhalf = (lane >> 4) * 16;
    const uint32_t aLane = (uint32_t)(wm * 64 + lrow) * ROWB + lhalf;
    const uint32_t bLane = (uint32_t)(wn * 32 + lrow) * ROWB + lhalf;

    for (int c = 0; c < NC; c++) {
        asm volatile("cp.async.wait_group 0;" ::: "memory");
        __syncthreads();

        const uint32_t st = sb + (uint32_t)(c & 1) * STAGEB;
        if (c + 1 < NC) {
            const int kn = (c + 1) * BK;
            load_stage(sb + (uint32_t)((c + 1) & 1) * STAGEB,
                       a0 + kn, a1 + kn, b0 + kn, b1 + kn, K, tid);
        }

        const uint32_t aBase = st + aLane;
        const uint32_t bBase = st + bLane;

#pragma unroll
        for (int ks = 0; ks < 4; ks++) {
            const uint32_t ko = ks * 32;   // 16 bf16 per k-step
            uint32_t bh[8], bl[8];
            ldsm4(bh[0], bh[1], bh[2], bh[3], bBase + OFF_BH + ko);
            ldsm4(bh[4], bh[5], bh[6], bh[7], bBase + OFF_BH + 16 * ROWB + ko);
            ldsm4(bl[0], bl[1], bl[2], bl[3], bBase + OFF_BL + ko);
            ldsm4(bl[4], bl[5], bl[6], bl[7], bBase + OFF_BL + 16 * ROWB + ko);

#pragma unroll
            for (int mt = 0; mt < 4; mt++) {
                uint32_t ah[4], al[4];
                ldsm4(ah[0], ah[1], ah[2], ah[3],
                      aBase + OFF_AH + (uint32_t)mt * 16 * ROWB + ko);
                ldsm4(al[0], al[1], al[2], al[3],
                      aBase + OFF_AL + (uint32_t)mt * 16 * ROWB + ko);
#pragma unroll
                for (int nt = 0; nt < 4; nt++) {
                    const uint32_t bb0 = bh[(nt >> 1) * 4 + (nt & 1)];
                    const uint32_t bb1 = bh[(nt >> 1) * 4 + (nt & 1) + 2];
                    const uint32_t cb0 = bl[(nt >> 1) * 4 + (nt & 1)];
                    const uint32_t cb1 = bl[(nt >> 1) * 4 + (nt & 1) + 2];
                    float* cc = acc[mt][nt];
                    mma16816(cc, ah[0], ah[1], ah[2], ah[3], bb0, bb1);  // Ah*Bh
                    mma16816(cc, al[0], al[1], al[2], al[3], bb0, bb1);  // Al*Bh
                    mma16816(cc, ah[0], ah[1], ah[2], ah[3], cb0, cb1);  // Ah*Bl
                }
            }
        }
    }

    // ---------------- epilogue ----------------
    const int crow = lane >> 2;          // 0..7
    const int ccol = (lane & 3) * 2;     // 0,2,4,6
#pragma unroll
    for (int mt = 0; mt < 4; mt++) {
#pragma unroll
        for (int nt = 0; nt < 4; nt++) {
            const float* cc = acc[mt][nt];
            const size_t m = m0 + wm * 64 + mt * 16 + crow;
            const size_t n = n0 + wn * 32 + nt * 8 + ccol;
            if (MODE == 0) {
                *reinterpret_cast<uint32_t*>(g_Hh + m * RANK_ + n) = pack_hi(cc[0], cc[1]);
                *reinterpret_cast<uint32_t*>(g_Hl + m * RANK_ + n) = pack_lo(cc[0], cc[1]);
                *reinterpret_cast<uint32_t*>(g_Hh + (m + 8) * RANK_ + n) = pack_hi(cc[2], cc[3]);
                *reinterpret_cast<uint32_t*>(g_Hl + (m + 8) * RANK_ + n) = pack_lo(cc[2], cc[3]);
            } else {
                const float bv0 = __ldg(bias + n), bv1 = __ldg(bias + n + 1);
                float2 o0 = { fmaxf(cc[0] + bv0, 0.0f), fmaxf(cc[1] + bv1, 0.0f) };
                float2 o1 = { fmaxf(cc[2] + bv0, 0.0f), fmaxf(cc[3] + bv1, 0.0f) };
                *reinterpret_cast<float2*>(out + m * UNITS_ + n) = o0;
                *reinterpret_cast<float2*>(out + (m + 8) * UNITS_ + n) = o1;
            }
        }
    }
}

// ---------------- launch ----------------
extern "C" void kernel_launch(void* const* d_in, const int* in_sizes, int n_in,
                              void* d_out, int out_size) {
    const float* X    = (const float*)d_in[0];
    const float* U    = (const float*)d_in[1];
    const float* S    = (const float*)d_in[2];
    const float* V    = (const float*)d_in[3];
    const float* bias = (const float*)d_in[4];
    float* out = (float*)d_out;

    void *pXh, *pXl, *pVh, *pVl;
    cudaGetSymbolAddress(&pXh, g_Xh);
    cudaGetSymbolAddress(&pXl, g_Xl);
    cudaGetSymbolAddress(&pVh, g_Vh);
    cudaGetSymbolAddress(&pVl, g_Vl);

    split_kernel<<<(MB_ * DIN_ / 4 + 255) / 256, 256>>>(
        X, (__nv_bfloat16*)pXh, (__nv_bfloat16*)pXl, MB_ * DIN_ / 4);
    split_kernel<<<(UNITS_ * RANK_ / 4 + 255) / 256, 256>>>(
        V, (__nv_bfloat16*)pVh, (__nv_bfloat16*)pVl, UNITS_ * RANK_ / 4);
    uprep_kernel<<<dim3(RANK_ / 32, DIN_ / 32), dim3(32, 8)>>>(U, S);

    cudaFuncSetAttribute(gemm_kernel<0>, cudaFuncAttributeMaxDynamicSharedMemorySize, SMEMB);
    cudaFuncSetAttribute(gemm_kernel<1>, cudaFuncAttributeMaxDynamicSharedMemorySize, SMEMB);

    // GEMM1: H = (X @ U) * S  (S folded into U^T), split-stored to g_Hh/g_Hl
    gemm_kernel<0><<<dim3(RANK_ / BN, MB_ / BM), NTHR, SMEMB>>>(nullptr, nullptr);
    // GEMM2: out = relu(H @ V^T + bias)
    gemm_kernel<1><<<dim3(UNITS_ / BN, MB_ / BM), NTHR, SMEMB>>>(bias, out);
}

// round 15
// speedup vs baseline: 1.4839x; 1.3491x over previous
#include <cuda_runtime.h>
#include <cuda_fp16.h>
#include <cstdint>

#define MB_    8192
#define DIN_   4096
#define RANK_  2048
#define UNITS_ 4096

#define BM 256
#define BN 128
#define BK 64
#define NTHR 512

// SMEM rows: 128B data padded to 144B (9 x 16B, gcd(9,8)=1) -> ldmatrix conflict-free
#define ROWB 144
#define ATILEB (256 * ROWB)              /* 36864 B */
#define BTILEB (128 * ROWB)              /* 18432 B */
#define STAGEB (2 * ATILEB + BTILEB)     /* 92160 B: Ah, Al, Bh */
#define SMEMB (2 * STAGEB)               /* 184320 B */
#define OFF_AH 0
#define OFF_AL ATILEB
#define OFF_BH (2 * ATILEB)

// ---------------- device scratch (no cudaMalloc allowed) ----------------
__device__ __half g_Xh[(size_t)MB_ * DIN_];
__device__ __half g_Xl[(size_t)MB_ * DIN_];
__device__ __half g_Uth[(size_t)RANK_ * DIN_];   // fp16 hi of (U*diag(S))^T, [RANK, DIN]
__device__ __half g_Vh[(size_t)UNITS_ * RANK_];  // fp16 hi of V, [N, K]
__device__ __half g_Hh[(size_t)MB_ * RANK_];
__device__ __half g_Hl[(size_t)MB_ * RANK_];

// ---------------- helpers ----------------
__device__ __forceinline__ uint32_t su32(const void* p) {
    uint32_t a;
    asm("{ .reg .u64 t; cvta.to.shared.u64 t, %1; cvt.u32.u64 %0, t; }" : "=r"(a) : "l"(p));
    return a;
}
__device__ __forceinline__ void cp16(uint32_t d, const void* g) {
    asm volatile("cp.async.cg.shared.global [%0], [%1], 16;" :: "r"(d), "l"(g));
}
__device__ __forceinline__ void ldsm4(uint32_t& r0, uint32_t& r1, uint32_t& r2, uint32_t& r3,
                                      uint32_t addr) {
    asm volatile("ldmatrix.sync.aligned.m8n8.x4.shared.b16 {%0,%1,%2,%3}, [%4];"
                 : "=r"(r0), "=r"(r1), "=r"(r2), "=r"(r3) : "r"(addr));
}
__device__ __forceinline__ void mma16816(float* c, uint32_t a0, uint32_t a1, uint32_t a2,
                                         uint32_t a3, uint32_t b0, uint32_t b1) {
    asm volatile(
        "mma.sync.aligned.m16n8k16.row.col.f32.f16.f16.f32 "
        "{%0,%1,%2,%3}, {%4,%5,%6,%7}, {%8,%9}, {%0,%1,%2,%3};"
        : "+f"(c[0]), "+f"(c[1]), "+f"(c[2]), "+f"(c[3])
        : "r"(a0), "r"(a1), "r"(a2), "r"(a3), "r"(b0), "r"(b1));
}
__device__ __forceinline__ uint32_t pack_hi(float x, float y) {
    __half2 t(__float2half_rn(x), __float2half_rn(y));
    return *reinterpret_cast<uint32_t*>(&t);
}
__device__ __forceinline__ uint32_t pack_lo(float x, float y) {
    __half hx = __float2half_rn(x), hy = __float2half_rn(y);
    __half2 t(__float2half_rn(x - __half2float(hx)),
              __float2half_rn(y - __half2float(hy)));
    return *reinterpret_cast<uint32_t*>(&t);
}

// ---------------- conversion kernels ----------------
// hi/lo split (for X)
__global__ void split_kernel(const float* __restrict__ src,
                             __half* __restrict__ hi,
                             __half* __restrict__ lo, int n4) {
    int i = blockIdx.x * blockDim.x + threadIdx.x;
    if (i >= n4) return;
    float4 v = reinterpret_cast<const float4*>(src)[i];
    uint2 hu = { pack_hi(v.x, v.y), pack_hi(v.z, v.w) };
    uint2 lu = { pack_lo(v.x, v.y), pack_lo(v.z, v.w) };
    reinterpret_cast<uint2*>(hi)[i] = hu;
    reinterpret_cast<uint2*>(lo)[i] = lu;
}

// hi-only conversion (for V)
__global__ void cvt_hi_kernel(const float* __restrict__ src,
                              __half* __restrict__ hi, int n4) {
    int i = blockIdx.x * blockDim.x + threadIdx.x;
    if (i >= n4) return;
    float4 v = reinterpret_cast<const float4*>(src)[i];
    uint2 hu = { pack_hi(v.x, v.y), pack_hi(v.z, v.w) };
    reinterpret_cast<uint2*>(hi)[i] = hu;
}

// Ut = (U * diag(S))^T, fp16 hi only.  U: [DIN, RANK] row-major.
__global__ void uprep_kernel(const float* __restrict__ U, const float* __restrict__ S) {
    __shared__ float t[32][33];
    int n0 = blockIdx.x * 32, k0 = blockIdx.y * 32;
    int tx = threadIdx.x, ty = threadIdx.y;
    float sv = S[n0 + tx];
#pragma unroll
    for (int i = 0; i < 4; i++)
        t[ty + i * 8][tx] = U[(size_t)(k0 + ty + i * 8) * RANK_ + n0 + tx] * sv;
    __syncthreads();
#pragma unroll
    for (int i = 0; i < 4; i++) {
        int n = n0 + ty + i * 8, k = k0 + tx;
        g_Uth[(size_t)n * DIN_ + k] = __float2half_rn(t[tx][ty + i * 8]);
    }
}

// ---------------- GEMM ----------------
// A tiles (hi+lo): 256 rows x 8 segs = 2048 cp16 each (4 iters of 512)
// B tile (hi): 128 rows x 8 segs = 1024 cp16 (2 iters of 512)
__device__ __forceinline__ void load_stage(uint32_t st,
                                           const __half* a0, const __half* a1,
                                           const __half* b0,
                                           int K, int tid) {
#pragma unroll
    for (int i = 0; i < 4; i++) {
        const int op = tid + i * 512;
        const int r = op >> 3, seg = op & 7;
        const uint32_t so = (uint32_t)r * ROWB + seg * 16;
        const size_t go = (size_t)r * K + seg * 8;
        cp16(st + OFF_AH + so, a0 + go);
        cp16(st + OFF_AL + so, a1 + go);
    }
#pragma unroll
    for (int i = 0; i < 2; i++) {
        const int op = tid + i * 512;
        const int r = op >> 3, seg = op & 7;
        const uint32_t so = (uint32_t)r * ROWB + seg * 16;
        const size_t go = (size_t)r * K + seg * 8;
        cp16(st + OFF_BH + so, b0 + go);
    }
    asm volatile("cp.async.commit_group;" ::: "memory");
}

template <int MODE>
__global__ void __launch_bounds__(NTHR, 1)
gemm_kernel(const float* __restrict__ bias, float* __restrict__ out) {
    constexpr int K = (MODE == 0) ? DIN_ : RANK_;
    constexpr int NC = K / BK;

    extern __shared__ __align__(128) char smem[];
    const uint32_t sb = su32(smem);
    const int tid = threadIdx.x;
    const int lane = tid & 31;
    const int warp = tid >> 5;       // 0..15
    const int wm = warp >> 2;        // 0..3  (64-row slabs)
    const int wn = warp & 3;         // 0..3  (32-col slabs)
    const size_t m0 = (size_t)blockIdx.y * BM;
    const size_t n0 = (size_t)blockIdx.x * BN;

    const __half *Ah, *Al, *Bh;
    if (MODE == 0) { Ah = g_Xh; Al = g_Xl; Bh = g_Uth; }
    else           { Ah = g_Hh; Al = g_Hl; Bh = g_Vh;  }
    const __half* a0 = Ah + m0 * K;
    const __half* a1 = Al + m0 * K;
    const __half* b0 = Bh + n0 * K;

    load_stage(sb, a0, a1, b0, K, tid);

    // warp tile 64x32: acc[mt 0..3][nt 0..3][4] = 64 regs
    float acc[4][4][4];
#pragma unroll
    for (int i = 0; i < 4; i++)
#pragma unroll
        for (int j = 0; j < 4; j++)
#pragma unroll
            for (int q = 0; q < 4; q++) acc[i][j][q] = 0.0f;

    const int lrow = lane & 15;
    const int lhalf = (lane >> 4) * 16;
    const uint32_t aLane = (uint32_t)(wm * 64 + lrow) * ROWB + lhalf;
    const uint32_t bLane = (uint32_t)(wn * 32 + lrow) * ROWB + lhalf;

    for (int c = 0; c < NC; c++) {
        asm volatile("cp.async.wait_group 0;" ::: "memory");
        __syncthreads();

        const uint32_t st = sb + (uint32_t)(c & 1) * STAGEB;
        if (c + 1 < NC) {
            const int kn = (c + 1) * BK;
            load_stage(sb + (uint32_t)((c + 1) & 1) * STAGEB,
                       a0 + kn, a1 + kn, b0 + kn, K, tid);
        }

        const uint32_t aBase = st + aLane;
        const uint32_t bBase = st + bLane;

#pragma unroll
        for (int ks = 0; ks < 4; ks++) {
            const uint32_t ko = ks * 32;   // 16 fp16 per k-step
            uint32_t bh[8];
            ldsm4(bh[0], bh[1], bh[2], bh[3], bBase + OFF_BH + ko);
            ldsm4(bh[4], bh[5], bh[6], bh[7], bBase + OFF_BH + 16 * ROWB + ko);

#pragma unroll
            for (int mt = 0; mt < 4; mt++) {
                uint32_t ah[4], al[4];
                ldsm4(ah[0], ah[1], ah[2], ah[3],
                      aBase + OFF_AH + (uint32_t)mt * 16 * ROWB + ko);
                ldsm4(al[0], al[1], al[2], al[3],
                      aBase + OFF_AL + (uint32_t)mt * 16 * ROWB + ko);
#pragma unroll
                for (int nt = 0; nt < 4; nt++) {
                    const uint32_t bb0 = bh[(nt >> 1) * 4 + (nt & 1)];
                    const uint32_t bb1 = bh[(nt >> 1) * 4 + (nt & 1) + 2];
                    float* cc = acc[mt][nt];
                    mma16816(cc, ah[0], ah[1], ah[2], ah[3], bb0, bb1);  // Ah*Bh
                    mma16816(cc, al[0], al[1], al[2], al[3], bb0, bb1);  // Al*Bh
                }
            }
        }
    }

    // ---------------- epilogue ----------------
    const int crow = lane >> 2;          // 0..7
    const int ccol = (lane & 3) * 2;     // 0,2,4,6
#pragma unroll
    for (int mt = 0; mt < 4; mt++) {
#pragma unroll
        for (int nt = 0; nt < 4; nt++) {
            const float* cc = acc[mt][nt];
            const size_t m = m0 + wm * 64 + mt * 16 + crow;
            const size_t n = n0 + wn * 32 + nt * 8 + ccol;
            if (MODE == 0) {
                *reinterpret_cast<uint32_t*>(g_Hh + m * RANK_ + n) = pack_hi(cc[0], cc[1]);
                *reinterpret_cast<uint32_t*>(g_Hl + m * RANK_ + n) = pack_lo(cc[0], cc[1]);
                *reinterpret_cast<uint32_t*>(g_Hh + (m + 8) * RANK_ + n) = pack_hi(cc[2], cc[3]);
                *reinterpret_cast<uint32_t*>(g_Hl + (m + 8) * RANK_ + n) = pack_lo(cc[2], cc[3]);
            } else {
                const float bv0 = __ldg(bias + n), bv1 = __ldg(bias + n + 1);
                float2 o0 = { fmaxf(cc[0] + bv0, 0.0f), fmaxf(cc[1] + bv1, 0.0f) };
                float2 o1 = { fmaxf(cc[2] + bv0, 0.0f), fmaxf(cc[3] + bv1, 0.0f) };
                *reinterpret_cast<float2*>(out + m * UNITS_ + n) = o0;
                *reinterpret_cast<float2*>(out + (m + 8) * UNITS_ + n) = o1;
            }
        }
    }
}

// ---------------- launch ----------------
extern "C" void kernel_launch(void* const* d_in, const int* in_sizes, int n_in,
                              void* d_out, int out_size) {
    const float* X    = (const float*)d_in[0];
    const float* U    = (const float*)d_in[1];
    const float* S    = (const float*)d_in[2];
    const float* V    = (const float*)d_in[3];
    const float* bias = (const float*)d_in[4];
    float* out = (float*)d_out;

    void *pXh, *pXl, *pVh;
    cudaGetSymbolAddress(&pXh, g_Xh);
    cudaGetSymbolAddress(&pXl, g_Xl);
    cudaGetSymbolAddress(&pVh, g_Vh);

    split_kernel<<<(MB_ * DIN_ / 4 + 255) / 256, 256>>>(
        X, (__half*)pXh, (__half*)pXl, MB_ * DIN_ / 4);
    cvt_hi_kernel<<<(UNITS_ * RANK_ / 4 + 255) / 256, 256>>>(
        V, (__half*)pVh, UNITS_ * RANK_ / 4);
    uprep_kernel<<<dim3(RANK_ / 32, DIN_ / 32), dim3(32, 8)>>>(U, S);

    cudaFuncSetAttribute(gemm_kernel<0>, cudaFuncAttributeMaxDynamicSharedMemorySize, SMEMB);
    cudaFuncSetAttribute(gemm_kernel<1>, cudaFuncAttributeMaxDynamicSharedMemorySize, SMEMB);

    // GEMM1: H = (X @ U) * S  (S folded into U^T hi), H split-stored fp16 hi/lo
    gemm_kernel<0><<<dim3(RANK_ / BN, MB_ / BM), NTHR, SMEMB>>>(nullptr, nullptr);
    // GEMM2: out = relu(H @ V^T + bias)
    gemm_kernel<1><<<dim3(UNITS_ / BN, MB_ / BM), NTHR, SMEMB>>>(bias, out);
}

// round 17
// speedup vs baseline: 1.9290x; 1.2999x over previous
#include <cuda_runtime.h>
#include <cuda_fp16.h>
#include <cstdint>

#define MB_    8192
#define DIN_   4096
#define RANK_  2048
#define UNITS_ 4096

#define BM 256
#define BN 128
#define BK 64
#define NTHR 512

// SMEM rows: 128B data padded to 144B (9 x 16B, gcd(9,8)=1) -> ldmatrix conflict-free
#define ROWB 144
#define ATILEB (256 * ROWB)              /* 36864 B */
#define BTILEB (128 * ROWB)              /* 18432 B */
// MODE0 stage: Ah, Al, Bh ; MODE1 stage: Ah, Bh
#define STAGEB0 (2 * ATILEB + BTILEB)    /* 92160 B */
#define STAGEB1 (ATILEB + BTILEB)        /* 55296 B */
#define SMEMB0 (2 * STAGEB0)             /* 184320 B */
#define SMEMB1 (2 * STAGEB1)             /* 110592 B */
#define OFF_AH 0
#define OFF_AL ATILEB                    /* MODE0 only */

// ---------------- device scratch (no cudaMalloc allowed) ----------------
__device__ __half g_Xh[(size_t)MB_ * DIN_];
__device__ __half g_Xl[(size_t)MB_ * DIN_];
__device__ __half g_Uth[(size_t)RANK_ * DIN_];   // fp16 hi of (U*diag(S))^T, [RANK, DIN]
__device__ __half g_Vh[(size_t)UNITS_ * RANK_];  // fp16 hi of V, [N, K]
__device__ __half g_Hh[(size_t)MB_ * RANK_];

// ---------------- helpers ----------------
__device__ __forceinline__ uint32_t su32(const void* p) {
    uint32_t a;
    asm("{ .reg .u64 t; cvta.to.shared.u64 t, %1; cvt.u32.u64 %0, t; }" : "=r"(a) : "l"(p));
    return a;
}
__device__ __forceinline__ void cp16(uint32_t d, const void* g) {
    asm volatile("cp.async.cg.shared.global [%0], [%1], 16;" :: "r"(d), "l"(g));
}
__device__ __forceinline__ void ldsm4(uint32_t& r0, uint32_t& r1, uint32_t& r2, uint32_t& r3,
                                      uint32_t addr) {
    asm volatile("ldmatrix.sync.aligned.m8n8.x4.shared.b16 {%0,%1,%2,%3}, [%4];"
                 : "=r"(r0), "=r"(r1), "=r"(r2), "=r"(r3) : "r"(addr));
}
__device__ __forceinline__ void mma16816(float* c, uint32_t a0, uint32_t a1, uint32_t a2,
                                         uint32_t a3, uint32_t b0, uint32_t b1) {
    asm volatile(
        "mma.sync.aligned.m16n8k16.row.col.f32.f16.f16.f32 "
        "{%0,%1,%2,%3}, {%4,%5,%6,%7}, {%8,%9}, {%0,%1,%2,%3};"
        : "+f"(c[0]), "+f"(c[1]), "+f"(c[2]), "+f"(c[3])
        : "r"(a0), "r"(a1), "r"(a2), "r"(a3), "r"(b0), "r"(b1));
}
__device__ __forceinline__ uint32_t pack_hi(float x, float y) {
    __half2 t(__float2half_rn(x), __float2half_rn(y));
    return *reinterpret_cast<uint32_t*>(&t);
}
__device__ __forceinline__ uint32_t pack_lo(float x, float y) {
    __half hx = __float2half_rn(x), hy = __float2half_rn(y);
    __half2 t(__float2half_rn(x - __half2float(hx)),
              __float2half_rn(y - __half2float(hy)));
    return *reinterpret_cast<uint32_t*>(&t);
}

// ---------------- conversion kernels ----------------
__global__ void split_kernel(const float* __restrict__ src,
                             __half* __restrict__ hi,
                             __half* __restrict__ lo, int n4) {
    int i = blockIdx.x * blockDim.x + threadIdx.x;
    if (i >= n4) return;
    float4 v = reinterpret_cast<const float4*>(src)[i];
    uint2 hu = { pack_hi(v.x, v.y), pack_hi(v.z, v.w) };
    uint2 lu = { pack_lo(v.x, v.y), pack_lo(v.z, v.w) };
    reinterpret_cast<uint2*>(hi)[i] = hu;
    reinterpret_cast<uint2*>(lo)[i] = lu;
}

__global__ void cvt_hi_kernel(const float* __restrict__ src,
                              __half* __restrict__ hi, int n4) {
    int i = blockIdx.x * blockDim.x + threadIdx.x;
    if (i >= n4) return;
    float4 v = reinterpret_cast<const float4*>(src)[i];
    uint2 hu = { pack_hi(v.x, v.y), pack_hi(v.z, v.w) };
    reinterpret_cast<uint2*>(hi)[i] = hu;
}

// Ut = (U * diag(S))^T, fp16 hi only.  U: [DIN, RANK] row-major.
__global__ void uprep_kernel(const float* __restrict__ U, const float* __restrict__ S) {
    __shared__ float t[32][33];
    int n0 = blockIdx.x * 32, k0 = blockIdx.y * 32;
    int tx = threadIdx.x, ty = threadIdx.y;
    float sv = S[n0 + tx];
#pragma unroll
    for (int i = 0; i < 4; i++)
        t[ty + i * 8][tx] = U[(size_t)(k0 + ty + i * 8) * RANK_ + n0 + tx] * sv;
    __syncthreads();
#pragma unroll
    for (int i = 0; i < 4; i++) {
        int n = n0 + ty + i * 8, k = k0 + tx;
        g_Uth[(size_t)n * DIN_ + k] = __float2half_rn(t[tx][ty + i * 8]);
    }
}

// ---------------- GEMM ----------------
template <int MODE>
__device__ __forceinline__ void load_stage(uint32_t st,
                                           const __half* a0, const __half* a1,
                                           const __half* b0,
                                           int K, int tid) {
    constexpr uint32_t OFF_B = (MODE == 0) ? (2 * ATILEB) : ATILEB;
#pragma unroll
    for (int i = 0; i < 4; i++) {
        const int op = tid + i * 512;
        const int r = op >> 3, seg = op & 7;
        const uint32_t so = (uint32_t)r * ROWB + seg * 16;
        const size_t go = (size_t)r * K + seg * 8;
        cp16(st + OFF_AH + so, a0 + go);
        if (MODE == 0) cp16(st + OFF_AL + so, a1 + go);
    }
#pragma unroll
    for (int i = 0; i < 2; i++) {
        const int op = tid + i * 512;
        const int r = op >> 3, seg = op & 7;
        const uint32_t so = (uint32_t)r * ROWB + seg * 16;
        const size_t go = (size_t)r * K + seg * 8;
        cp16(st + OFF_B + so, b0 + go);
    }
    asm volatile("cp.async.commit_group;" ::: "memory");
}

template <int MODE>
__global__ void __launch_bounds__(NTHR, 1)
gemm_kernel(const float* __restrict__ bias, float* __restrict__ out) {
    constexpr int K = (MODE == 0) ? DIN_ : RANK_;
    constexpr int NC = K / BK;
    constexpr uint32_t STG = (MODE == 0) ? STAGEB0 : STAGEB1;
    constexpr uint32_t OFF_B = (MODE == 0) ? (2 * ATILEB) : ATILEB;

    extern __shared__ __align__(128) char smem[];
    const uint32_t sb = su32(smem);
    const int tid = threadIdx.x;
    const int lane = tid & 31;
    const int warp = tid >> 5;       // 0..15
    const int wm = warp >> 2;        // 0..3  (64-row slabs)
    const int wn = warp & 3;         // 0..3  (32-col slabs)
    const size_t m0 = (size_t)blockIdx.y * BM;
    const size_t n0 = (size_t)blockIdx.x * BN;

    const __half *Ah, *Al, *Bh;
    if (MODE == 0) { Ah = g_Xh; Al = g_Xl; Bh = g_Uth; }
    else           { Ah = g_Hh; Al = nullptr; Bh = g_Vh; }
    const __half* a0 = Ah + m0 * K;
    const __half* a1 = (MODE == 0) ? (Al + m0 * K) : nullptr;
    const __half* b0 = Bh + n0 * K;

    load_stage<MODE>(sb, a0, a1, b0, K, tid);

    // warp tile 64x32: acc[mt 0..3][nt 0..3][4] = 64 regs
    float acc[4][4][4];
#pragma unroll
    for (int i = 0; i < 4; i++)
#pragma unroll
        for (int j = 0; j < 4; j++)
#pragma unroll
            for (int q = 0; q < 4; q++) acc[i][j][q] = 0.0f;

    const int lrow = lane & 15;
    const int lhalf = (lane >> 4) * 16;
    const uint32_t aLane = (uint32_t)(wm * 64 + lrow) * ROWB + lhalf;
    const uint32_t bLane = (uint32_t)(wn * 32 + lrow) * ROWB + lhalf;

    for (int c = 0; c < NC; c++) {
        asm volatile("cp.async.wait_group 0;" ::: "memory");
        __syncthreads();

        const uint32_t st = sb + (uint32_t)(c & 1) * STG;
        if (c + 1 < NC) {
            const int kn = (c + 1) * BK;
            load_stage<MODE>(sb + (uint32_t)((c + 1) & 1) * STG,
                             a0 + kn, (MODE == 0) ? (a1 + kn) : nullptr, b0 + kn, K, tid);
        }

        const uint32_t aBase = st + aLane;
        const uint32_t bBase = st + bLane;

#pragma unroll
        for (int ks = 0; ks < 4; ks++) {
            const uint32_t ko = ks * 32;   // 16 fp16 per k-step
            uint32_t bh[8];
            ldsm4(bh[0], bh[1], bh[2], bh[3], bBase + OFF_B + ko);
            ldsm4(bh[4], bh[5], bh[6], bh[7], bBase + OFF_B + 16 * ROWB + ko);

#pragma unroll
            for (int mt = 0; mt < 4; mt++) {
                uint32_t ah[4];
                ldsm4(ah[0], ah[1], ah[2], ah[3],
                      aBase + OFF_AH + (uint32_t)mt * 16 * ROWB + ko);
                uint32_t al[4];
                if (MODE == 0)
                    ldsm4(al[0], al[1], al[2], al[3],
                          aBase + OFF_AL + (uint32_t)mt * 16 * ROWB + ko);
#pragma unroll
                for (int nt = 0; nt < 4; nt++) {
                    const uint32_t bb0 = bh[(nt >> 1) * 4 + (nt & 1)];
                    const uint32_t bb1 = bh[(nt >> 1) * 4 + (nt & 1) + 2];
                    float* cc = acc[mt][nt];
                    mma16816(cc, ah[0], ah[1], ah[2], ah[3], bb0, bb1);      // Ah*Bh
                    if (MODE == 0)
                        mma16816(cc, al[0], al[1], al[2], al[3], bb0, bb1);  // Al*Bh
                }
            }
        }
    }

    // ---------------- epilogue ----------------
    const int crow = lane >> 2;          // 0..7
    const int ccol = (lane & 3) * 2;     // 0,2,4,6
#pragma unroll
    for (int mt = 0; mt < 4; mt++) {
#pragma unroll
        for (int nt = 0; nt < 4; nt++) {
            const float* cc = acc[mt][nt];
            const size_t m = m0 + wm * 64 + mt * 16 + crow;
            const size_t n = n0 + wn * 32 + nt * 8 + ccol;
            if (MODE == 0) {
                *reinterpret_cast<uint32_t*>(g_Hh + m * RANK_ + n) = pack_hi(cc[0], cc[1]);
                *reinterpret_cast<uint32_t*>(g_Hh + (m + 8) * RANK_ + n) = pack_hi(cc[2], cc[3]);
            } else {
                const float bv0 = __ldg(bias + n), bv1 = __ldg(bias + n + 1);
                float2 o0 = { fmaxf(cc[0] + bv0, 0.0f), fmaxf(cc[1] + bv1, 0.0f) };
                float2 o1 = { fmaxf(cc[2] + bv0, 0.0f), fmaxf(cc[3] + bv1, 0.0f) };
                *reinterpret_cast<float2*>(out + m * UNITS_ + n) = o0;
                *reinterpret_cast<float2*>(out + (m + 8) * UNITS_ + n) = o1;
            }
        }
    }
}

// ---------------- launch ----------------
extern "C" void kernel_launch(void* const* d_in, const int* in_sizes, int n_in,
                              void* d_out, int out_size) {
    const float* X    = (const float*)d_in[0];
    const float* U    = (const float*)d_in[1];
    const float* S    = (const float*)d_in[2];
    const float* V    = (const float*)d_in[3];
    const float* bias = (const float*)d_in[4];
    float* out = (float*)d_out;

    void *pXh, *pXl, *pVh;
    cudaGetSymbolAddress(&pXh, g_Xh);
    cudaGetSymbolAddress(&pXl, g_Xl);
    cudaGetSymbolAddress(&pVh, g_Vh);

    split_kernel<<<(MB_ * DIN_ / 4 + 255) / 256, 256>>>(
        X, (__half*)pXh, (__half*)pXl, MB_ * DIN_ / 4);
    cvt_hi_kernel<<<(UNITS_ * RANK_ / 4 + 255) / 256, 256>>>(
        V, (__half*)pVh, UNITS_ * RANK_ / 4);
    uprep_kernel<<<dim3(RANK_ / 32, DIN_ / 32), dim3(32, 8)>>>(U, S);

    cudaFuncSetAttribute(gemm_kernel<0>, cudaFuncAttributeMaxDynamicSharedMemorySize, SMEMB0);
    cudaFuncSetAttribute(gemm_kernel<1>, cudaFuncAttributeMaxDynamicSharedMemorySize, SMEMB1);

    // GEMM1 (2-pass): H = (X @ U) * S  (S folded into U^T hi), H stored fp16 hi
    gemm_kernel<0><<<dim3(RANK_ / BN, MB_ / BM), NTHR, SMEMB0>>>(nullptr, nullptr);
    // GEMM2 (1-pass): out = relu(H @ V^T + bias)
    gemm_kernel<1><<<dim3(UNITS_ / BN, MB_ / BM), NTHR, SMEMB1>>>(bias, out);
}